// round 1
// baseline (speedup 1.0000x reference)
#include <cuda_runtime.h>

// decoderTriNet: phi_hat[b,n,k] = sum_j c_tri[j] * d2_j(tau), where
// tau = remainder(t_k_hat[b,k] - n, 128) and d2_j is the fp32 second
// difference of relu(tau + b_tri[.]) exactly as the reference computes it.
// In exact arithmetic only ~2 knots per element are nonzero (hat basis);
// in fp32 there are additional tiny residues exactly at binade crossings
// of s = tau - b[j]. We evaluate the reference formula bit-faithfully on:
//   - an 8-knot window around the hat (s ~ 0)
//   - 4-knot windows at each crossing s = v for v in {128,64,32,16,8,4}
// Windows are >= 256 knots apart -> never overlap -> no double counting.
//
// One warp per output element; lane l handles candidate slot l (32 slots).

#define DTN_B 16
#define DTN_N 128
#define DTN_K 8
#define DTN_NJ 8192   // len(c_tri); len(b_tri) = 8194
#define DTN_OUT (DTN_B * DTN_N * DTN_K)   // 16384

__global__ __launch_bounds__(256, 8)
void decoderTriNet_kernel(const float* __restrict__ tk,   // [B*K] = 128
                          const float* __restrict__ ct,   // [8192]
                          const float* __restrict__ bt,   // [8194]
                          float* __restrict__ out)        // [B*N*K] = 16384
{
    const int warp = (blockIdx.x * blockDim.x + threadIdx.x) >> 5;
    const int lane = threadIdx.x & 31;
    if (warp >= DTN_OUT) return;

    // warp -> (b, n, k), row-major [B, N, K]
    const int b   = warp >> 10;          // / (N*K)
    const int rem = warp & 1023;
    const int n   = rem >> 3;            // / K
    const int k   = rem & 7;

    // tau = remainder(t - n, 128), replicating fp32 rounding of the reference:
    // one fp32 subtract, then (if negative) one fp32 add of 128.
    const float t = __ldg(&tk[b * DTN_K + k]);
    const float r = t - (float)n;
    const float tau = (r < 0.0f) ? (r + 128.0f) : r;

    // Candidate knot index for this lane.
    // s_i = tau + b_tri[i] crosses value v at i = 64*(tau - v) + 4096.5.
    // Hat (s = 0) is centered at i0 = 64*tau + 4096.5.
    int j;
    if (lane < 24) {
        const int w = lane >> 2;                     // 0..5
        const float v = (float)(128 >> w);           // 128,64,32,16,8,4
        const float fi = fmaf(64.0f, tau - v, 4096.5f);
        j = (int)floorf(fi) - 2 + (lane & 3);        // window [iv-2, iv+1]
    } else {
        const float fi = fmaf(64.0f, tau, 4096.5f);
        j = (int)floorf(fi) - 3 + (lane - 24);       // window [i0-3, i0+4]
    }

    float contrib = 0.0f;
    if (j >= 0 && j < DTN_NJ) {
        // Bit-faithful replication of the reference inner math:
        //   x_i = relu(fl(tau + b_tri[i]))
        //   d2  = fl(fl(x0 - 2*x1) + x2)    (x0 - 2*x1 == FMA(-2,x1,x0) exactly)
        const float x0 = fmaxf(tau + __ldg(&bt[j]),     0.0f);
        const float x1 = fmaxf(tau + __ldg(&bt[j + 1]), 0.0f);
        const float x2 = fmaxf(tau + __ldg(&bt[j + 2]), 0.0f);
        const float d2 = (x0 - 2.0f * x1) + x2;
        contrib = d2 * __ldg(&ct[j]);
    }

    // Warp reduction
    #pragma unroll
    for (int off = 16; off; off >>= 1)
        contrib += __shfl_xor_sync(0xffffffffu, contrib, off);

    if (lane == 0)
        out[warp] = contrib;
}

extern "C" void kernel_launch(void* const* d_in, const int* in_sizes, int n_in,
                              void* d_out, int out_size)
{
    // Route inputs by element count for robustness:
    //   t_k_hat: 128, c_tri: 8192, b_tri: 8194
    const float* tk = nullptr;
    const float* ct = nullptr;
    const float* bt = nullptr;
    for (int i = 0; i < n_in; ++i) {
        if      (in_sizes[i] == DTN_B * DTN_K) tk = (const float*)d_in[i];
        else if (in_sizes[i] == DTN_NJ)        ct = (const float*)d_in[i];
        else if (in_sizes[i] == DTN_NJ + 2)    bt = (const float*)d_in[i];
    }

    float* out = (float*)d_out;
    const int total_threads = DTN_OUT * 32;     // one warp per output
    const int block = 256;
    const int grid = (total_threads + block - 1) / block;   // 2048
    decoderTriNet_kernel<<<grid, block>>>(tk, ct, bt, out);
}

// round 2
// speedup vs baseline: 1.2029x; 1.2029x over previous
#include <cuda_runtime.h>

// decoderTriNet: phi_hat[b,n,k] = sum_j c_tri[j] * d2_j(tau),
//   tau = remainder(t_k_hat[b,k] - n, 128),
//   d2_j = fp32 second difference of relu(tau + b_tri[j..j+2]).
//
// fp32 model (validated bit-exact in round 1, rel_err = 0.0):
//  - b[j] are exact multiples of 2^-7; rounding error of fl(tau - b[j]) is a
//    pure function of the binade of s = tau - b[j]  ->  the second difference
//    cancels everywhere EXCEPT:
//      * the relu kink (s ~ 0): nonzero at j in {c0-1, c0}
//      * each binade crossing s = v, v in {128,64,32,16,8,4}: nonzero at
//        j in {c_v-1, c_v}
//    where c_v = floor(fmaf(64, tau - v, 4095.5)) is EXACT in fp32
//    (operands span <= 24 bit positions, single rounding of a representable
//    value). Windows are >= 256 knots apart -> never overlap.
//
// Slots per output: 6 crossings x 2 + 4-slot hat window (margin +-1) = 16.
// => 16 lanes per output, TWO outputs per warp, 4-step shfl reduction.

#define DTN_B 16
#define DTN_N 128
#define DTN_K 8
#define DTN_NJ 8192                       // len(c_tri); len(b_tri) = 8194
#define DTN_OUT (DTN_B * DTN_N * DTN_K)   // 16384

__global__ __launch_bounds__(256, 8)
void decoderTriNet_kernel(const float* __restrict__ tk,   // [B*K] = 128
                          const float* __restrict__ ct,   // [8192]
                          const float* __restrict__ bt,   // [8194]
                          float* __restrict__ out)        // [B*N*K] = 16384
{
    const int warp = (blockIdx.x * blockDim.x + threadIdx.x) >> 5;
    const int lane = threadIdx.x & 31;
    const int half = lane >> 4;          // which of the 2 outputs in this warp
    const int sl   = lane & 15;          // slot within the output

    const int idx = (warp << 1) | half;  // output index in [0, 16384)
    // idx -> (b, n, k), row-major [B, N, K]; tk index = b*K + k
    const int n = (idx >> 3) & (DTN_N - 1);
    const int tkidx = ((idx >> 10) << 3) | (idx & 7);

    // tau = remainder(t - n, 128), replicating the reference's fp32 rounding.
    const float t = __ldg(&tk[tkidx]);
    const float r = t - (float)n;
    const float tau = (r < 0.0f) ? (r + 128.0f) : r;

    // Candidate knot index for this slot.
    int j;
    if (sl < 12) {
        const float v  = (float)(128 >> (sl >> 1));           // 128..4
        const float fi = fmaf(64.0f, tau - v, 4095.5f);       // exact
        j = (int)floorf(fi) - 1 + (sl & 1);                   // {c-1, c}
    } else {
        const float fi = fmaf(64.0f, tau, 4095.5f);           // exact
        j = (int)floorf(fi) - 2 + (sl - 12);                  // [c0-2, c0+1]
    }

    float contrib = 0.0f;
    if (j >= 0 && j < DTN_NJ) {
        // Bit-faithful replication of the reference inner math.
        const float x0 = fmaxf(tau + __ldg(&bt[j]),     0.0f);
        const float x1 = fmaxf(tau + __ldg(&bt[j + 1]), 0.0f);
        const float x2 = fmaxf(tau + __ldg(&bt[j + 2]), 0.0f);
        const float d2 = (x0 - 2.0f * x1) + x2;
        contrib = d2 * __ldg(&ct[j]);
    }

    // Reduce across the 16 lanes of this output (xor offsets stay in-half).
    contrib += __shfl_xor_sync(0xffffffffu, contrib, 8);
    contrib += __shfl_xor_sync(0xffffffffu, contrib, 4);
    contrib += __shfl_xor_sync(0xffffffffu, contrib, 2);
    contrib += __shfl_xor_sync(0xffffffffu, contrib, 1);

    if (sl == 0)
        out[idx] = contrib;
}

extern "C" void kernel_launch(void* const* d_in, const int* in_sizes, int n_in,
                              void* d_out, int out_size)
{
    // Route inputs by element count:
    //   t_k_hat: 128, c_tri: 8192, b_tri: 8194
    const float* tk = nullptr;
    const float* ct = nullptr;
    const float* bt = nullptr;
    for (int i = 0; i < n_in; ++i) {
        if      (in_sizes[i] == DTN_B * DTN_K) tk = (const float*)d_in[i];
        else if (in_sizes[i] == DTN_NJ)        ct = (const float*)d_in[i];
        else if (in_sizes[i] == DTN_NJ + 2)    bt = (const float*)d_in[i];
    }

    float* out = (float*)d_out;
    const int total_threads = DTN_OUT * 16;          // 16 lanes per output
    const int block = 256;
    const int grid = (total_threads + block - 1) / block;   // 1024
    decoderTriNet_kernel<<<grid, block>>>(tk, ct, bt, out);
}